// round 1
// baseline (speedup 1.0000x reference)
#include <cuda_runtime.h>
#include <math.h>

#define N_NODES 100000
#define N_EDGES 1600000
#define IN_F    128
#define HF      64
#define OUTF    40
#define EPSB    1e-5f

// ---------------- scratch (device globals; no allocation allowed) -------------
__device__ __align__(16) float g_h [N_NODES * HF];   // h1, then h2
__device__ __align__(16) float g_a [N_NODES * HF];   // agg1 -> x1_pre -> x1
__device__ __align__(16) float g_a2[N_NODES * HF];   // agg2
__device__ float g_dinv[N_NODES];
__device__ int   g_deg [N_NODES];
__device__ float g_sum [HF];
__device__ float g_sumsq[HF];
__device__ float g_scale[HF];
__device__ float g_shift[HF];
__device__ int   g_is64;

// ---------------- dtype autodetect for edge_index ----------------------------
// If values are int64 (< 100000), every odd 32-bit word is 0. For int32 data,
// the chance that 64 random values in [0,100000) are all zero is ~0.
__global__ void k_detect(const int* ei32) {
    if (blockIdx.x == 0 && threadIdx.x == 0) {
        int all0 = 1;
        for (int i = 0; i < 64; i++)
            if (ei32[2 * i + 1] != 0) { all0 = 0; break; }
        g_is64 = all0;
    }
}

__device__ __forceinline__ void load_edge(const void* ei, int e, int& s, int& d) {
    if (g_is64) {
        const long long* p = (const long long*)ei;
        s = (int)p[e];
        d = (int)p[N_EDGES + e];
    } else {
        const int* p = (const int*)ei;
        s = p[e];
        d = p[N_EDGES + e];
    }
}

// ---------------- zero scratch ------------------------------------------------
__global__ void k_zero() {
    int tid = blockIdx.x * blockDim.x + threadIdx.x;
    int stride = gridDim.x * blockDim.x;
    const int total4 = (N_NODES * HF) / 4;
    float4 z4 = make_float4(0.f, 0.f, 0.f, 0.f);
    for (int i = tid; i < total4; i += stride) {
        ((float4*)g_a)[i]  = z4;
        ((float4*)g_a2)[i] = z4;
    }
    for (int i = tid; i < N_NODES; i += stride) g_deg[i] = 0;
    if (tid < HF) { g_sum[tid] = 0.f; g_sumsq[tid] = 0.f; }
}

// ---------------- degree + dinv -----------------------------------------------
__global__ void k_deg(const void* ei) {
    int e = blockIdx.x * blockDim.x + threadIdx.x;
    if (e < N_EDGES) {
        int s, d;
        load_edge(ei, e, s, d);
        atomicAdd(&g_deg[d], 1);
    }
}

__global__ void k_dinv() {
    int n = blockIdx.x * blockDim.x + threadIdx.x;
    if (n < N_NODES) g_dinv[n] = rsqrtf((float)g_deg[n] + 1.0f);
}

// ---------------- GEMM1: g_h = x0 @ W1  (N x 128 @ 128 x 64) ------------------
__global__ void k_gemm1(const float* __restrict__ x0, const float* __restrict__ W1) {
    // W transposed in smem: Wt[col][k], padded row of 132 words so float4 reads
    // are conflict-free (phase banks 0,4,...,28).
    __shared__ __align__(16) float Wt[HF * 132];
    __shared__ __align__(16) float xs[4][IN_F];

    for (int i = threadIdx.x; i < IN_F * HF; i += blockDim.x) {
        int k = i / HF, c = i % HF;
        Wt[c * 132 + k] = W1[i];
    }
    __syncthreads();

    int g = threadIdx.x >> 6, col = threadIdx.x & 63;
    for (int row0 = blockIdx.x * 4; row0 < N_NODES; row0 += gridDim.x * 4) {
        int row = row0 + g;
        __syncthreads();
        if (row < N_NODES) {
            xs[g][col]      = x0[row * IN_F + col];
            xs[g][col + 64] = x0[row * IN_F + col + 64];
        }
        __syncthreads();
        if (row < N_NODES) {
            float acc = 0.f;
            const float4* wv = (const float4*)(Wt + col * 132);
            const float4* xv = (const float4*)xs[g];
#pragma unroll
            for (int k4 = 0; k4 < 32; k4++) {
                float4 w = wv[k4];
                float4 x = xv[k4];
                acc += w.x * x.x + w.y * x.y + w.z * x.z + w.w * x.w;
            }
            g_h[row * HF + col] = acc;
        }
    }
}

// ---------------- edge scatter: agg[dst] += h[src] * dinv[src]*dinv[dst] ------
// 16 threads per edge, float4 load + 4 scalar RED adds each.
__global__ void k_scatter(const void* ei, int layer) {
    int t = blockIdx.x * blockDim.x + threadIdx.x;
    int lane16 = t & 15;
    int e = t >> 4;
    if (e >= N_EDGES) return;
    int s, d;
    load_edge(ei, e, s, d);
    float norm = g_dinv[s] * g_dinv[d];
    const float4* hv = (const float4*)(g_h + s * HF);
    float4 v = hv[lane16];
    float* agg = (layer == 0) ? g_a : g_a2;
    float* p = agg + d * HF + lane16 * 4;
    atomicAdd(p + 0, v.x * norm);
    atomicAdd(p + 1, v.y * norm);
    atomicAdd(p + 2, v.z * norm);
    atomicAdd(p + 3, v.w * norm);
}

// ---------------- finish layer1 + BN stats ------------------------------------
// x1_pre = agg1 + h1 * dinv^2 + b1 (stored back in g_a), accumulate per-channel
// sum / sumsq. Stride is a multiple of 64, so each thread's channel is fixed.
__global__ void k_finish1(const float* __restrict__ b1) {
    int tid = blockIdx.x * blockDim.x + threadIdx.x;
    int stride = gridDim.x * blockDim.x;
    int f = tid & 63;
    float bf = b1[f];
    float s = 0.f, s2 = 0.f;
    for (int i = tid; i < N_NODES * HF; i += stride) {
        int row = i >> 6;
        float di = g_dinv[row];
        float v = g_a[i] + g_h[i] * di * di + bf;
        g_a[i] = v;
        s += v;
        s2 += v * v;
    }
    __shared__ float sh0[256], sh1[256];
    sh0[threadIdx.x] = s;
    sh1[threadIdx.x] = s2;
    __syncthreads();
    if (threadIdx.x < 64) {
        float a = 0.f, b = 0.f;
        for (int j = threadIdx.x; j < 256; j += 64) { a += sh0[j]; b += sh1[j]; }
        atomicAdd(&g_sum[threadIdx.x], a);
        atomicAdd(&g_sumsq[threadIdx.x], b);
    }
}

__global__ void k_stats(const float* __restrict__ g1, const float* __restrict__ be1) {
    int f = threadIdx.x;
    if (f < HF) {
        float mu  = g_sum[f] * (1.0f / N_NODES);
        float var = g_sumsq[f] * (1.0f / N_NODES) - mu * mu;
        float rs  = rsqrtf(var + EPSB);
        float sc  = rs * g1[f];
        g_scale[f] = sc;
        g_shift[f] = be1[f] - mu * sc;
    }
}

// ---------------- BN + relu + GEMM2: x1 -> g_a ; h2 = x1 @ W2 -> g_h ---------
__global__ void k_layer2(const float* __restrict__ W2) {
    __shared__ __align__(16) float Wt[HF * 68];  // [col][k], pad 68
    __shared__ __align__(16) float xs[4][HF];
    __shared__ float sc[HF], sf[HF];

    for (int i = threadIdx.x; i < HF * HF; i += blockDim.x) {
        int k = i / HF, c = i % HF;
        Wt[c * 68 + k] = W2[i];
    }
    if (threadIdx.x < HF) {
        sc[threadIdx.x] = g_scale[threadIdx.x];
        sf[threadIdx.x] = g_shift[threadIdx.x];
    }
    __syncthreads();

    int g = threadIdx.x >> 6, col = threadIdx.x & 63;
    for (int row0 = blockIdx.x * 4; row0 < N_NODES; row0 += gridDim.x * 4) {
        int row = row0 + g;
        __syncthreads();
        if (row < N_NODES) {
            float v = g_a[row * HF + col] * sc[col] + sf[col];
            v = fmaxf(v, 0.f);
            g_a[row * HF + col] = v;   // x1
            xs[g][col] = v;
        }
        __syncthreads();
        if (row < N_NODES) {
            float acc = 0.f;
            const float4* wv = (const float4*)(Wt + col * 68);
            const float4* xv = (const float4*)xs[g];
#pragma unroll
            for (int k4 = 0; k4 < 16; k4++) {
                float4 w = wv[k4];
                float4 x = xv[k4];
                acc += w.x * x.x + w.y * x.y + w.z * x.z + w.w * x.w;
            }
            g_h[row * HF + col] = acc;   // h2
        }
    }
}

// ---------------- head: x2 = agg2 + h2*dinv^2 + b2; out = logsoftmax([x1|x2]Wl+bl)
__global__ void k_final(const float* __restrict__ Wl, const float* __restrict__ bl,
                        const float* __restrict__ b2, float* __restrict__ out) {
    __shared__ __align__(16) float Wt[OUTF * 132];  // [j][k], pad 132
    __shared__ float bls[OUTF], b2s[HF];
    __shared__ __align__(16) float cv[8][IN_F];

    for (int i = threadIdx.x; i < IN_F * OUTF; i += blockDim.x) {
        int k = i / OUTF, j = i % OUTF;
        Wt[j * 132 + k] = Wl[i];
    }
    if (threadIdx.x < OUTF) bls[threadIdx.x] = bl[threadIdx.x];
    if (threadIdx.x < HF)   b2s[threadIdx.x] = b2[threadIdx.x];
    __syncthreads();

    int w = threadIdx.x >> 5, lane = threadIdx.x & 31;
    for (int row = blockIdx.x * 8 + w; row < N_NODES; row += gridDim.x * 8) {
        float di = g_dinv[row];
        float d2 = di * di;
        cv[w][lane]      = g_a[row * HF + lane];
        cv[w][lane + 32] = g_a[row * HF + 32 + lane];
        cv[w][64 + lane] = g_a2[row * HF + lane]      + g_h[row * HF + lane]      * d2 + b2s[lane];
        cv[w][96 + lane] = g_a2[row * HF + 32 + lane] + g_h[row * HF + 32 + lane] * d2 + b2s[32 + lane];
        __syncwarp();

        int j1 = lane, j2 = 32 + (lane & 7);
        float o1 = bls[j1], o2 = bls[j2];
        const float4* w1v = (const float4*)(Wt + j1 * 132);
        const float4* w2v = (const float4*)(Wt + j2 * 132);
        const float4* cvv = (const float4*)cv[w];
#pragma unroll
        for (int k4 = 0; k4 < 32; k4++) {
            float4 c = cvv[k4];
            float4 a = w1v[k4];
            o1 += c.x * a.x + c.y * a.y + c.z * a.z + c.w * a.w;
            float4 b = w2v[k4];
            o2 += c.x * b.x + c.y * b.y + c.z * b.z + c.w * b.w;
        }
        float o2m = (lane < 8) ? o2 : -INFINITY;
        float m = fmaxf(o1, o2m);
        for (int off = 16; off; off >>= 1) m = fmaxf(m, __shfl_xor_sync(~0u, m, off));
        float s = expf(o1 - m) + ((lane < 8) ? expf(o2 - m) : 0.f);
        for (int off = 16; off; off >>= 1) s += __shfl_xor_sync(~0u, s, off);
        float lse = m + logf(s);
        out[row * OUTF + j1] = o1 - lse;
        if (lane < 8) out[row * OUTF + j2] = o2 - lse;
        __syncwarp();
    }
}

// ---------------- launch ------------------------------------------------------
extern "C" void kernel_launch(void* const* d_in, const int* in_sizes, int n_in,
                              void* d_out, int out_size) {
    const float* x0  = (const float*)d_in[0];
    const void*  ei  = d_in[1];                 // int64 or int32, autodetected
    const float* W1  = (const float*)d_in[2];
    const float* b1  = (const float*)d_in[3];
    const float* g1  = (const float*)d_in[4];
    const float* be1 = (const float*)d_in[5];
    const float* W2  = (const float*)d_in[6];
    const float* b2  = (const float*)d_in[7];
    const float* Wl  = (const float*)d_in[8];
    const float* bl  = (const float*)d_in[9];
    float* out = (float*)d_out;

    k_detect<<<1, 32>>>((const int*)ei);
    k_zero<<<256, 256>>>();
    k_deg<<<(N_EDGES + 255) / 256, 256>>>(ei);
    k_dinv<<<(N_NODES + 255) / 256, 256>>>();
    k_gemm1<<<888, 256>>>(x0, W1);
    k_scatter<<<(N_EDGES * 16) / 256, 256>>>(ei, 0);
    k_finish1<<<512, 256>>>(b1);
    k_stats<<<1, 64>>>(g1, be1);
    k_layer2<<<1184, 256>>>(W2);
    k_scatter<<<(N_EDGES * 16) / 256, 256>>>(ei, 1);
    k_final<<<1184, 256>>>(Wl, bl, b2, out);
}

// round 3
// speedup vs baseline: 2.3231x; 2.3231x over previous
#include <cuda_runtime.h>
#include <math.h>

#define N_NODES 100000
#define N_EDGES 1600000
#define IN_F    128
#define HF      64
#define OUTF    40
#define EPSB    1e-5f

// ---------------- scratch (device globals; no allocation) ---------------------
__device__ __align__(16) float g_h  [N_NODES * HF];   // h1, then h2
__device__ __align__(16) float g_a  [N_NODES * HF];   // x1_pre -> x1
__device__ __align__(16) float g_a2 [N_NODES * HF];   // x2
__device__ float g_dinv[N_NODES];
__device__ int   g_deg [N_NODES];
__device__ int   g_rowloc[N_NODES];
__device__ int   g_rowstart[N_NODES + 1];
__device__ int   g_cursor[N_NODES];
__device__ int   g_btot[128];
__device__ int   g_boff[128];
__device__ int   g_src32[N_EDGES];
__device__ int   g_dst32[N_EDGES];
__device__ int   g_esrc [N_EDGES];
__device__ float g_enorm[N_EDGES];
__device__ float g_sum [HF];
__device__ float g_sumsq[HF];
__device__ float g_scale[HF];
__device__ float g_shift[HF];
__device__ int   g_is64;

// ---------------- zero + dtype autodetect ------------------------------------
__global__ void k_zero_detect(const int* ei32) {
    int i = blockIdx.x * blockDim.x + threadIdx.x;
    if (i < N_NODES) g_deg[i] = 0;
    if (i < HF) { g_sum[i] = 0.f; g_sumsq[i] = 0.f; }
    if (i == 0) {
        int all0 = 1;
        for (int t = 0; t < 64; t++)
            if (ei32[2 * t + 1] != 0) { all0 = 0; break; }
        g_is64 = all0;
    }
}

// ---------------- degree count + int32 conversion -----------------------------
__global__ void k_deg_cvt(const void* ei) {
    int e = blockIdx.x * blockDim.x + threadIdx.x;
    if (e >= N_EDGES) return;
    int s, d;
    if (g_is64) {
        const long long* p = (const long long*)ei;
        s = (int)p[e];
        d = (int)p[N_EDGES + e];
    } else {
        const int* p = (const int*)ei;
        s = p[e];
        d = p[N_EDGES + e];
    }
    g_src32[e] = s;
    g_dst32[e] = d;
    atomicAdd(&g_deg[d], 1);
}

// ---------------- 3-phase exclusive scan over degrees --------------------------
__global__ void k_scanA() {
    __shared__ int sh[1024];
    int t = threadIdx.x;
    int i = blockIdx.x * 1024 + t;
    int v = (i < N_NODES) ? g_deg[i] : 0;
    sh[t] = v;
    __syncthreads();
    for (int off = 1; off < 1024; off <<= 1) {
        int x = (t >= off) ? sh[t - off] : 0;
        __syncthreads();
        sh[t] += x;
        __syncthreads();
    }
    if (i < N_NODES) g_rowloc[i] = sh[t] - v;
    if (t == 1023) g_btot[blockIdx.x] = sh[t];
}

__global__ void k_scanB() {
    __shared__ int sh[128];
    int t = threadIdx.x;
    int v = (t < 98) ? g_btot[t] : 0;
    sh[t] = v;
    __syncthreads();
    for (int off = 1; off < 128; off <<= 1) {
        int x = (t >= off) ? sh[t - off] : 0;
        __syncthreads();
        sh[t] += x;
        __syncthreads();
    }
    if (t < 98) g_boff[t] = sh[t] - v;
}

__global__ void k_scanC() {
    int i = blockIdx.x * blockDim.x + threadIdx.x;
    if (i < N_NODES) {
        int base = g_rowloc[i] + g_boff[i >> 10];
        g_rowstart[i] = base;
        g_cursor[i] = base;
        g_dinv[i] = rsqrtf((float)g_deg[i] + 1.0f);
    }
    if (i == 0) g_rowstart[N_NODES] = N_EDGES;
}

// ---------------- bucket fill: CSR by dst -------------------------------------
__global__ void k_bucket() {
    int e = blockIdx.x * blockDim.x + threadIdx.x;
    if (e >= N_EDGES) return;
    int s = g_src32[e];
    int d = g_dst32[e];
    int pos = atomicAdd(&g_cursor[d], 1);
    g_esrc[pos] = s;
    g_enorm[pos] = g_dinv[s] * g_dinv[d];
}

// ---------------- GEMM1: g_h = x0 @ W1 (100000x128 @ 128x64) -------------------
__global__ void k_gemm1(const float* __restrict__ x0, const float* __restrict__ W1) {
    __shared__ __align__(16) float Wt[HF * 132];
    __shared__ __align__(16) float4 xs[16 * 32];   // [16 rows][128]

    int tid = threadIdx.x;
    for (int i = tid; i < IN_F * HF; i += 128) {
        int k = i >> 6, c = i & 63;
        Wt[c * 132 + k] = W1[i];
    }
    __syncthreads();

    int w = tid >> 5, lane = tid & 31;
    int c = (w & 1) * 32 + lane;
    int rg = (w >> 1) * 8;
    const float4* wv = (const float4*)(Wt + c * 132);

    for (int tile = blockIdx.x * 16; tile < N_NODES; tile += gridDim.x * 16) {
        __syncthreads();
        for (int i = tid; i < 16 * 32; i += 128) {
            int r = i >> 5, c4 = i & 31;
            xs[i] = ((const float4*)(x0 + (size_t)(tile + r) * IN_F))[c4];
        }
        __syncthreads();
        float acc[8] = {0, 0, 0, 0, 0, 0, 0, 0};
#pragma unroll 4
        for (int k4 = 0; k4 < 32; k4++) {
            float4 wq = wv[k4];
#pragma unroll
            for (int r = 0; r < 8; r++) {
                float4 xq = xs[(rg + r) * 32 + k4];
                acc[r] += wq.x * xq.x + wq.y * xq.y + wq.z * xq.z + wq.w * xq.w;
            }
        }
#pragma unroll
        for (int r = 0; r < 8; r++)
            g_h[(size_t)(tile + rg + r) * HF + c] = acc[r];
    }
}

// ---------------- aggregation: out[n] = sum_{e->n} h[src]*norm + h[n]*d2 + b ---
// warp per node; lane owns float2 of features. Buffers selected INSIDE the
// kernel (device globals must never be passed as host-side kernel args).
__global__ void k_agg(int layer, const float* __restrict__ bias) {
    const float* h = g_h;
    float* out = (layer == 0) ? g_a : g_a2;
    int n = blockIdx.x * 8 + (threadIdx.x >> 5);
    int lane = threadIdx.x & 31;
    int rs = g_rowstart[n];
    int re = g_rowstart[n + 1];
    float ax = 0.f, ay = 0.f;

    for (int j0 = rs; j0 < re; j0 += 32) {
        int idx = j0 + lane;
        int s = 0; float nrm = 0.f;
        if (idx < re) { s = g_esrc[idx]; nrm = g_enorm[idx]; }
        int cnt = min(32, re - j0);
        int t = 0;
        for (; t + 4 <= cnt; t += 4) {
            int s0 = __shfl_sync(0xffffffffu, s, t);
            int s1 = __shfl_sync(0xffffffffu, s, t + 1);
            int s2 = __shfl_sync(0xffffffffu, s, t + 2);
            int s3 = __shfl_sync(0xffffffffu, s, t + 3);
            float n0 = __shfl_sync(0xffffffffu, nrm, t);
            float n1 = __shfl_sync(0xffffffffu, nrm, t + 1);
            float n2 = __shfl_sync(0xffffffffu, nrm, t + 2);
            float n3 = __shfl_sync(0xffffffffu, nrm, t + 3);
            float2 v0 = *(const float2*)(h + (size_t)s0 * HF + lane * 2);
            float2 v1 = *(const float2*)(h + (size_t)s1 * HF + lane * 2);
            float2 v2 = *(const float2*)(h + (size_t)s2 * HF + lane * 2);
            float2 v3 = *(const float2*)(h + (size_t)s3 * HF + lane * 2);
            ax = fmaf(v0.x, n0, ax); ay = fmaf(v0.y, n0, ay);
            ax = fmaf(v1.x, n1, ax); ay = fmaf(v1.y, n1, ay);
            ax = fmaf(v2.x, n2, ax); ay = fmaf(v2.y, n2, ay);
            ax = fmaf(v3.x, n3, ax); ay = fmaf(v3.y, n3, ay);
        }
        for (; t < cnt; t++) {
            int st = __shfl_sync(0xffffffffu, s, t);
            float nt = __shfl_sync(0xffffffffu, nrm, t);
            float2 v = *(const float2*)(h + (size_t)st * HF + lane * 2);
            ax = fmaf(v.x, nt, ax); ay = fmaf(v.y, nt, ay);
        }
    }
    float di = g_dinv[n];
    float d2 = di * di;
    float2 hv = *(const float2*)(h + (size_t)n * HF + lane * 2);
    float2 bv = *(const float2*)(bias + lane * 2);
    float2 o;
    o.x = ax + hv.x * d2 + bv.x;
    o.y = ay + hv.y * d2 + bv.y;
    *(float2*)(out + (size_t)n * HF + lane * 2) = o;
}

// ---------------- BN stats over g_a -------------------------------------------
__global__ void k_stats1() {
    int tid = blockIdx.x * blockDim.x + threadIdx.x;
    const int stride = 256 * 256;   // multiple of 64 -> fixed channel per thread
    float s = 0.f, s2 = 0.f;
    for (int i = tid; i < N_NODES * HF; i += stride) {
        float v = g_a[i];
        s += v;
        s2 += v * v;
    }
    __shared__ float sh0[256], sh1[256];
    sh0[threadIdx.x] = s;
    sh1[threadIdx.x] = s2;
    __syncthreads();
    if (threadIdx.x < 64) {
        float a = 0.f, b = 0.f;
        for (int j = threadIdx.x; j < 256; j += 64) { a += sh0[j]; b += sh1[j]; }
        atomicAdd(&g_sum[threadIdx.x], a);
        atomicAdd(&g_sumsq[threadIdx.x], b);
    }
}

__global__ void k_stats2(const float* __restrict__ g1, const float* __restrict__ be1) {
    int f = threadIdx.x;
    if (f < HF) {
        float mu  = g_sum[f] * (1.0f / N_NODES);
        float var = g_sumsq[f] * (1.0f / N_NODES) - mu * mu;
        float sc  = rsqrtf(var + EPSB) * g1[f];
        g_scale[f] = sc;
        g_shift[f] = be1[f] - mu * sc;
    }
}

// ---------------- GEMM2: BN+relu(g_a) -> x1 (back to g_a); h2 = x1 @ W2 -> g_h -
__global__ void k_gemm2(const float* __restrict__ W2) {
    __shared__ __align__(16) float Wt[HF * 68];
    __shared__ __align__(16) float4 xs[16 * 16];   // [16 rows][64]
    __shared__ __align__(16) float4 s_sc[16], s_sf[16];

    int tid = threadIdx.x;
    for (int i = tid; i < HF * HF; i += 128) {
        int k = i >> 6, c = i & 63;
        Wt[c * 68 + k] = W2[i];
    }
    if (tid < 16) {
        s_sc[tid] = ((const float4*)g_scale)[tid];
        s_sf[tid] = ((const float4*)g_shift)[tid];
    }
    __syncthreads();

    int w = tid >> 5, lane = tid & 31;
    int c = (w & 1) * 32 + lane;
    int rg = (w >> 1) * 8;
    const float4* wv = (const float4*)(Wt + c * 68);

    for (int tile = blockIdx.x * 16; tile < N_NODES; tile += gridDim.x * 16) {
        __syncthreads();
        for (int i = tid; i < 16 * 16; i += 128) {
            int r = i >> 4, c4 = i & 15;
            size_t off = (size_t)(tile + r) * HF;
            float4 a = ((const float4*)(g_a + off))[c4];
            float4 sc = s_sc[c4], sf = s_sf[c4];
            float4 v;
            v.x = fmaxf(a.x * sc.x + sf.x, 0.f);
            v.y = fmaxf(a.y * sc.y + sf.y, 0.f);
            v.z = fmaxf(a.z * sc.z + sf.z, 0.f);
            v.w = fmaxf(a.w * sc.w + sf.w, 0.f);
            xs[i] = v;
            ((float4*)(g_a + off))[c4] = v;   // x1 for the head
        }
        __syncthreads();
        float acc[8] = {0, 0, 0, 0, 0, 0, 0, 0};
#pragma unroll 4
        for (int k4 = 0; k4 < 16; k4++) {
            float4 wq = wv[k4];
#pragma unroll
            for (int r = 0; r < 8; r++) {
                float4 xq = xs[(rg + r) * 16 + k4];
                acc[r] += wq.x * xq.x + wq.y * xq.y + wq.z * xq.z + wq.w * xq.w;
            }
        }
#pragma unroll
        for (int r = 0; r < 8; r++)
            g_h[(size_t)(tile + rg + r) * HF + c] = acc[r];
    }
}

// ---------------- head: logits = [x1|x2] @ Wl + bl; out = log_softmax ---------
__global__ void k_final(const float* __restrict__ Wl, const float* __restrict__ bl,
                        float* __restrict__ out) {
    __shared__ float xs[32 * 129];                  // concat features, pad 129
    __shared__ __align__(16) float Wlt[OUTF * 132]; // [j][k]
    __shared__ float ls[32 * 44];                   // logits
    __shared__ float bls[OUTF];

    int tid = threadIdx.x;
    for (int i = tid; i < IN_F * OUTF; i += 256) {
        int k = i / OUTF, j = i % OUTF;
        Wlt[j * 132 + k] = Wl[i];
    }
    if (tid < OUTF) bls[tid] = bl[tid];

    int row0 = blockIdx.x * 32;
    for (int i = tid; i < 32 * 32; i += 256) {
        int r = i >> 5, c4 = i & 31;
        float4 v = (c4 < 16)
            ? ((const float4*)(g_a  + (size_t)(row0 + r) * HF))[c4]
            : ((const float4*)(g_a2 + (size_t)(row0 + r) * HF))[c4 - 16];
        float* p = xs + r * 129 + c4 * 4;
        p[0] = v.x; p[1] = v.y; p[2] = v.z; p[3] = v.w;
    }
    __syncthreads();

    int w = tid >> 5, r = tid & 31;
    int j0 = w * 5;
    float acc[5] = {0, 0, 0, 0, 0};
    const float* xr = xs + r * 129;
#pragma unroll 4
    for (int k4 = 0; k4 < 32; k4++) {
        float x0 = xr[4 * k4 + 0];
        float x1 = xr[4 * k4 + 1];
        float x2 = xr[4 * k4 + 2];
        float x3 = xr[4 * k4 + 3];
#pragma unroll
        for (int cc = 0; cc < 5; cc++) {
            float4 wq = ((const float4*)(Wlt + (j0 + cc) * 132))[k4];
            acc[cc] += x0 * wq.x + x1 * wq.y + x2 * wq.z + x3 * wq.w;
        }
    }
#pragma unroll
    for (int cc = 0; cc < 5; cc++)
        ls[r * 44 + j0 + cc] = acc[cc] + bls[j0 + cc];
    __syncthreads();

    // softmax: 8 threads per row (octets within warps), 5 cols each
    int rr = tid >> 3, oo = tid & 7;
    const float* lr = ls + rr * 44 + oo * 5;
    float m = -INFINITY;
#pragma unroll
    for (int cc = 0; cc < 5; cc++) m = fmaxf(m, lr[cc]);
    for (int off = 4; off; off >>= 1) m = fmaxf(m, __shfl_xor_sync(0xffffffffu, m, off));
    float s = 0.f;
#pragma unroll
    for (int cc = 0; cc < 5; cc++) s += __expf(lr[cc] - m);
    for (int off = 4; off; off >>= 1) s += __shfl_xor_sync(0xffffffffu, s, off);
    float lse = m + __logf(s);
    float* op = out + (size_t)(row0 + rr) * OUTF + oo * 5;
#pragma unroll
    for (int cc = 0; cc < 5; cc++) op[cc] = lr[cc] - lse;
}

// ---------------- launch ------------------------------------------------------
extern "C" void kernel_launch(void* const* d_in, const int* in_sizes, int n_in,
                              void* d_out, int out_size) {
    const float* x0  = (const float*)d_in[0];
    const void*  ei  = d_in[1];
    const float* W1  = (const float*)d_in[2];
    const float* b1  = (const float*)d_in[3];
    const float* g1  = (const float*)d_in[4];
    const float* be1 = (const float*)d_in[5];
    const float* W2  = (const float*)d_in[6];
    const float* b2  = (const float*)d_in[7];
    const float* Wl  = (const float*)d_in[8];
    const float* bl  = (const float*)d_in[9];
    float* out = (float*)d_out;

    k_zero_detect<<<98, 1024>>>((const int*)ei);
    k_deg_cvt<<<6250, 256>>>(ei);
    k_scanA<<<98, 1024>>>();
    k_scanB<<<1, 128>>>();
    k_scanC<<<98, 1024>>>();
    k_bucket<<<6250, 256>>>();
    k_gemm1<<<740, 128>>>(x0, W1);
    k_agg<<<12500, 256>>>(0, b1);
    k_stats1<<<256, 256>>>();
    k_stats2<<<1, 64>>>(g1, be1);
    k_gemm2<<<1480, 128>>>(W2);
    k_agg<<<12500, 256>>>(1, b2);
    k_final<<<3125, 256>>>(Wl, bl, out);
}

// round 4
// speedup vs baseline: 2.3709x; 1.0206x over previous
#include <cuda_runtime.h>
#include <math.h>

#define N_NODES 100000
#define N_EDGES 1600000
#define IN_F    128
#define HF      64
#define OUTF    40
#define EPSB    1e-5f

// ---------------- f32x2 packed-FMA helpers (Blackwell dual fp32 per issue) ----
union F4U { float4 f; unsigned long long u[2]; };

__device__ __forceinline__ unsigned long long ffma2(unsigned long long a,
                                                    unsigned long long b,
                                                    unsigned long long c) {
    unsigned long long d;
    asm("fma.rn.f32x2 %0, %1, %2, %3;" : "=l"(d) : "l"(a), "l"(b), "l"(c));
    return d;
}

__device__ __forceinline__ float2 u2f(unsigned long long v) {
    float2 f;
    asm("mov.b64 {%0, %1}, %2;" : "=f"(f.x), "=f"(f.y) : "l"(v));
    return f;
}

// ---------------- scratch (device globals; no allocation) ---------------------
__device__ __align__(16) float g_h  [N_NODES * HF];   // h1, then h2
__device__ __align__(16) float g_a  [N_NODES * HF];   // x1_pre -> x1
__device__ __align__(16) float g_a2 [N_NODES * HF];   // x2
__device__ float g_dinv[N_NODES];
__device__ int   g_deg [N_NODES];
__device__ int   g_rowloc[N_NODES];
__device__ int   g_rowstart[N_NODES + 1];
__device__ int   g_cursor[N_NODES];
__device__ int   g_btot[128];
__device__ int   g_boff[128];
__device__ int   g_src32[N_EDGES];
__device__ int   g_dst32[N_EDGES];
__device__ int   g_esrc [N_EDGES];
__device__ float g_enorm[N_EDGES];
__device__ float g_sum [HF];
__device__ float g_sumsq[HF];
__device__ int   g_is64;

// ---------------- zero + dtype autodetect ------------------------------------
__global__ void k_zero_detect(const int* ei32) {
    int i = blockIdx.x * blockDim.x + threadIdx.x;
    if (i < N_NODES) g_deg[i] = 0;
    if (i < HF) { g_sum[i] = 0.f; g_sumsq[i] = 0.f; }
    if (i == 0) {
        int all0 = 1;
        for (int t = 0; t < 64; t++)
            if (ei32[2 * t + 1] != 0) { all0 = 0; break; }
        g_is64 = all0;
    }
}

// ---------------- degree count + int32 conversion -----------------------------
__global__ void k_deg_cvt(const void* ei) {
    int e = blockIdx.x * blockDim.x + threadIdx.x;
    if (e >= N_EDGES) return;
    int s, d;
    if (g_is64) {
        const long long* p = (const long long*)ei;
        s = (int)p[e];
        d = (int)p[N_EDGES + e];
    } else {
        const int* p = (const int*)ei;
        s = p[e];
        d = p[N_EDGES + e];
    }
    g_src32[e] = s;
    g_dst32[e] = d;
    atomicAdd(&g_deg[d], 1);
}

// ---------------- 3-phase exclusive scan over degrees --------------------------
__global__ void k_scanA() {
    __shared__ int sh[1024];
    int t = threadIdx.x;
    int i = blockIdx.x * 1024 + t;
    int v = (i < N_NODES) ? g_deg[i] : 0;
    sh[t] = v;
    __syncthreads();
    for (int off = 1; off < 1024; off <<= 1) {
        int x = (t >= off) ? sh[t - off] : 0;
        __syncthreads();
        sh[t] += x;
        __syncthreads();
    }
    if (i < N_NODES) g_rowloc[i] = sh[t] - v;
    if (t == 1023) g_btot[blockIdx.x] = sh[t];
}

__global__ void k_scanB() {
    __shared__ int sh[128];
    int t = threadIdx.x;
    int v = (t < 98) ? g_btot[t] : 0;
    sh[t] = v;
    __syncthreads();
    for (int off = 1; off < 128; off <<= 1) {
        int x = (t >= off) ? sh[t - off] : 0;
        __syncthreads();
        sh[t] += x;
        __syncthreads();
    }
    if (t < 98) g_boff[t] = sh[t] - v;
}

__global__ void k_scanC() {
    int i = blockIdx.x * blockDim.x + threadIdx.x;
    if (i < N_NODES) {
        int base = g_rowloc[i] + g_boff[i >> 10];
        g_rowstart[i] = base;
        g_cursor[i] = base;
        g_dinv[i] = rsqrtf((float)g_deg[i] + 1.0f);
    }
    if (i == 0) g_rowstart[N_NODES] = N_EDGES;
}

// ---------------- bucket fill: CSR by dst -------------------------------------
__global__ void k_bucket() {
    int e = blockIdx.x * blockDim.x + threadIdx.x;
    if (e >= N_EDGES) return;
    int s = g_src32[e];
    int d = g_dst32[e];
    int pos = atomicAdd(&g_cursor[d], 1);
    g_esrc[pos] = s;
    g_enorm[pos] = g_dinv[s] * g_dinv[d];
}

// ---------------- GEMM1: g_h = x0 @ W1 (100000x128 @ 128x64) -------------------
// 128 thr; 16-row tile; lane=col, acc 8 rows; f32x2 packed FMA.
__global__ void k_gemm1(const float* __restrict__ x0, const float* __restrict__ W1) {
    __shared__ __align__(16) float Wt[HF * 132];
    __shared__ __align__(16) float4 xs[16 * 32];   // [16 rows][128]

    int tid = threadIdx.x;
    for (int i = tid; i < IN_F * HF; i += 128) {
        int k = i >> 6, c = i & 63;
        Wt[c * 132 + k] = W1[i];
    }
    __syncthreads();

    int w = tid >> 5, lane = tid & 31;
    int c = (w & 1) * 32 + lane;
    int rg = (w >> 1) * 8;
    const float4* wv = (const float4*)(Wt + c * 132);

    for (int tile = blockIdx.x * 16; tile < N_NODES; tile += gridDim.x * 16) {
        __syncthreads();
        for (int i = tid; i < 16 * 32; i += 128) {
            int r = i >> 5, c4 = i & 31;
            xs[i] = ((const float4*)(x0 + (size_t)(tile + r) * IN_F))[c4];
        }
        __syncthreads();
        unsigned long long al[8] = {0, 0, 0, 0, 0, 0, 0, 0};
        unsigned long long ah[8] = {0, 0, 0, 0, 0, 0, 0, 0};
#pragma unroll 4
        for (int k4 = 0; k4 < 32; k4++) {
            F4U wq; wq.f = wv[k4];
#pragma unroll
            for (int r = 0; r < 8; r++) {
                F4U xq; xq.f = xs[(rg + r) * 32 + k4];
                al[r] = ffma2(wq.u[0], xq.u[0], al[r]);
                ah[r] = ffma2(wq.u[1], xq.u[1], ah[r]);
            }
        }
#pragma unroll
        for (int r = 0; r < 8; r++) {
            float2 a = u2f(al[r]), b = u2f(ah[r]);
            g_h[(size_t)(tile + rg + r) * HF + c] = (a.x + a.y) + (b.x + b.y);
        }
    }
}

// ---------------- aggregation: out[n] = sum_{e->n} h[src]*norm + h[n]*d2 + b ---
// warp per node; lane owns float2 of features. Scratch selected in-kernel.
__global__ void k_agg(int layer, const float* __restrict__ bias) {
    const float* h = g_h;
    float* out = (layer == 0) ? g_a : g_a2;
    int n = blockIdx.x * 8 + (threadIdx.x >> 5);
    int lane = threadIdx.x & 31;
    int rs = g_rowstart[n];
    int re = g_rowstart[n + 1];
    float ax = 0.f, ay = 0.f;

    for (int j0 = rs; j0 < re; j0 += 32) {
        int idx = j0 + lane;
        int s = 0; float nrm = 0.f;
        if (idx < re) { s = g_esrc[idx]; nrm = g_enorm[idx]; }
        int cnt = min(32, re - j0);
        int t = 0;
        for (; t + 4 <= cnt; t += 4) {
            int s0 = __shfl_sync(0xffffffffu, s, t);
            int s1 = __shfl_sync(0xffffffffu, s, t + 1);
            int s2 = __shfl_sync(0xffffffffu, s, t + 2);
            int s3 = __shfl_sync(0xffffffffu, s, t + 3);
            float n0 = __shfl_sync(0xffffffffu, nrm, t);
            float n1 = __shfl_sync(0xffffffffu, nrm, t + 1);
            float n2 = __shfl_sync(0xffffffffu, nrm, t + 2);
            float n3 = __shfl_sync(0xffffffffu, nrm, t + 3);
            float2 v0 = *(const float2*)(h + (size_t)s0 * HF + lane * 2);
            float2 v1 = *(const float2*)(h + (size_t)s1 * HF + lane * 2);
            float2 v2 = *(const float2*)(h + (size_t)s2 * HF + lane * 2);
            float2 v3 = *(const float2*)(h + (size_t)s3 * HF + lane * 2);
            ax = fmaf(v0.x, n0, ax); ay = fmaf(v0.y, n0, ay);
            ax = fmaf(v1.x, n1, ax); ay = fmaf(v1.y, n1, ay);
            ax = fmaf(v2.x, n2, ax); ay = fmaf(v2.y, n2, ay);
            ax = fmaf(v3.x, n3, ax); ay = fmaf(v3.y, n3, ay);
        }
        for (; t < cnt; t++) {
            int st = __shfl_sync(0xffffffffu, s, t);
            float nt = __shfl_sync(0xffffffffu, nrm, t);
            float2 v = *(const float2*)(h + (size_t)st * HF + lane * 2);
            ax = fmaf(v.x, nt, ax); ay = fmaf(v.y, nt, ay);
        }
    }
    float di = g_dinv[n];
    float d2 = di * di;
    float2 hv = *(const float2*)(h + (size_t)n * HF + lane * 2);
    float2 bv = *(const float2*)(bias + lane * 2);
    float2 o;
    o.x = ax + hv.x * d2 + bv.x;
    o.y = ay + hv.y * d2 + bv.y;
    *(float2*)(out + (size_t)n * HF + lane * 2) = o;
}

// ---------------- BN stats over g_a -------------------------------------------
__global__ void k_stats1() {
    int tid = blockIdx.x * blockDim.x + threadIdx.x;
    const int stride = 256 * 256;   // multiple of 64 -> fixed channel per thread
    float s = 0.f, s2 = 0.f;
    for (int i = tid; i < N_NODES * HF; i += stride) {
        float v = g_a[i];
        s += v;
        s2 += v * v;
    }
    __shared__ float sh0[256], sh1[256];
    sh0[threadIdx.x] = s;
    sh1[threadIdx.x] = s2;
    __syncthreads();
    if (threadIdx.x < 64) {
        float a = 0.f, b = 0.f;
        for (int j = threadIdx.x; j < 256; j += 64) { a += sh0[j]; b += sh1[j]; }
        atomicAdd(&g_sum[threadIdx.x], a);
        atomicAdd(&g_sumsq[threadIdx.x], b);
    }
}

// ---------------- GEMM2: BN+relu(g_a) -> x1 (to g_a); h2 = x1 @ W2 -> g_h ------
// BN scale/shift recomputed per block from g_sum/g_sumsq (64 rsqrt, trivial).
__global__ void k_gemm2(const float* __restrict__ W2,
                        const float* __restrict__ g1, const float* __restrict__ be1) {
    __shared__ __align__(16) float Wt[HF * 68];
    __shared__ __align__(16) float4 xs[16 * 16];   // [16 rows][64]
    __shared__ __align__(16) float s_sc[HF], s_sf[HF];

    int tid = threadIdx.x;
    for (int i = tid; i < HF * HF; i += 128) {
        int k = i >> 6, c = i & 63;
        Wt[c * 68 + k] = W2[i];
    }
    if (tid < HF) {
        float mu  = g_sum[tid] * (1.0f / N_NODES);
        float var = g_sumsq[tid] * (1.0f / N_NODES) - mu * mu;
        float sc  = rsqrtf(var + EPSB) * g1[tid];
        s_sc[tid] = sc;
        s_sf[tid] = be1[tid] - mu * sc;
    }
    __syncthreads();

    int w = tid >> 5, lane = tid & 31;
    int c = (w & 1) * 32 + lane;
    int rg = (w >> 1) * 8;
    const float4* wv = (const float4*)(Wt + c * 68);

    for (int tile = blockIdx.x * 16; tile < N_NODES; tile += gridDim.x * 16) {
        __syncthreads();
        for (int i = tid; i < 16 * 16; i += 128) {
            int r = i >> 4, c4 = i & 15;
            size_t off = (size_t)(tile + r) * HF;
            float4 a = ((const float4*)(g_a + off))[c4];
            float4 sc = ((const float4*)s_sc)[c4];
            float4 sf = ((const float4*)s_sf)[c4];
            float4 v;
            v.x = fmaxf(a.x * sc.x + sf.x, 0.f);
            v.y = fmaxf(a.y * sc.y + sf.y, 0.f);
            v.z = fmaxf(a.z * sc.z + sf.z, 0.f);
            v.w = fmaxf(a.w * sc.w + sf.w, 0.f);
            xs[i] = v;
            ((float4*)(g_a + off))[c4] = v;   // x1 for the head
        }
        __syncthreads();
        unsigned long long al[8] = {0, 0, 0, 0, 0, 0, 0, 0};
        unsigned long long ah[8] = {0, 0, 0, 0, 0, 0, 0, 0};
#pragma unroll 4
        for (int k4 = 0; k4 < 16; k4++) {
            F4U wq; wq.f = wv[k4];
#pragma unroll
            for (int r = 0; r < 8; r++) {
                F4U xq; xq.f = xs[(rg + r) * 16 + k4];
                al[r] = ffma2(wq.u[0], xq.u[0], al[r]);
                ah[r] = ffma2(wq.u[1], xq.u[1], ah[r]);
            }
        }
#pragma unroll
        for (int r = 0; r < 8; r++) {
            float2 a = u2f(al[r]), b = u2f(ah[r]);
            g_h[(size_t)(tile + rg + r) * HF + c] = (a.x + a.y) + (b.x + b.y);
        }
    }
}

// ---------------- head: logits = [x1|x2] @ Wl + bl; out = log_softmax ---------
// 256 thr; 32-row tile; lane=row (xs pad 132 -> conflict-free LDS.128);
// warp owns 5 output cols; f32x2 packed FMA.
__global__ void k_final(const float* __restrict__ Wl, const float* __restrict__ bl,
                        float* __restrict__ out) {
    __shared__ __align__(16) float xs[32 * 132];    // concat features, pad 132
    __shared__ __align__(16) float Wlt[OUTF * 132]; // [j][k]
    __shared__ float ls[32 * 44];                   // logits
    __shared__ float bls[OUTF];

    int tid = threadIdx.x;
    for (int i = tid; i < IN_F * OUTF; i += 256) {
        int k = i / OUTF, j = i % OUTF;
        Wlt[j * 132 + k] = Wl[i];
    }
    if (tid < OUTF) bls[tid] = bl[tid];

    int row0 = blockIdx.x * 32;
    for (int i = tid; i < 32 * 32; i += 256) {
        int r = i >> 5, c4 = i & 31;
        float4 v = (c4 < 16)
            ? ((const float4*)(g_a  + (size_t)(row0 + r) * HF))[c4]
            : ((const float4*)(g_a2 + (size_t)(row0 + r) * HF))[c4 - 16];
        ((float4*)(xs + r * 132))[c4] = v;
    }
    __syncthreads();

    int w = tid >> 5, r = tid & 31;
    int j0 = w * 5;
    unsigned long long al[5] = {0, 0, 0, 0, 0};
    unsigned long long ah[5] = {0, 0, 0, 0, 0};
    const float4* xrv = (const float4*)(xs + r * 132);
#pragma unroll 4
    for (int k4 = 0; k4 < 32; k4++) {
        F4U xq; xq.f = xrv[k4];
#pragma unroll
        for (int cc = 0; cc < 5; cc++) {
            F4U wq; wq.f = ((const float4*)(Wlt + (j0 + cc) * 132))[k4];
            al[cc] = ffma2(xq.u[0], wq.u[0], al[cc]);
            ah[cc] = ffma2(xq.u[1], wq.u[1], ah[cc]);
        }
    }
#pragma unroll
    for (int cc = 0; cc < 5; cc++) {
        float2 a = u2f(al[cc]), b = u2f(ah[cc]);
        ls[r * 44 + j0 + cc] = (a.x + a.y) + (b.x + b.y) + bls[j0 + cc];
    }
    __syncthreads();

    // softmax: 8 threads per row (octets within warps), 5 cols each
    int rr = tid >> 3, oo = tid & 7;
    const float* lr = ls + rr * 44 + oo * 5;
    float m = -INFINITY;
#pragma unroll
    for (int cc = 0; cc < 5; cc++) m = fmaxf(m, lr[cc]);
    for (int off = 4; off; off >>= 1) m = fmaxf(m, __shfl_xor_sync(0xffffffffu, m, off));
    float s = 0.f;
#pragma unroll
    for (int cc = 0; cc < 5; cc++) s += __expf(lr[cc] - m);
    for (int off = 4; off; off >>= 1) s += __shfl_xor_sync(0xffffffffu, s, off);
    float lse = m + __logf(s);
    float* op = out + (size_t)(row0 + rr) * OUTF + oo * 5;
#pragma unroll
    for (int cc = 0; cc < 5; cc++) op[cc] = lr[cc] - lse;
}

// ---------------- launch ------------------------------------------------------
extern "C" void kernel_launch(void* const* d_in, const int* in_sizes, int n_in,
                              void* d_out, int out_size) {
    const float* x0  = (const float*)d_in[0];
    const void*  ei  = d_in[1];
    const float* W1  = (const float*)d_in[2];
    const float* b1  = (const float*)d_in[3];
    const float* g1  = (const float*)d_in[4];
    const float* be1 = (const float*)d_in[5];
    const float* W2  = (const float*)d_in[6];
    const float* b2  = (const float*)d_in[7];
    const float* Wl  = (const float*)d_in[8];
    const float* bl  = (const float*)d_in[9];
    float* out = (float*)d_out;

    k_zero_detect<<<98, 1024>>>((const int*)ei);
    k_deg_cvt<<<6250, 256>>>(ei);
    k_scanA<<<98, 1024>>>();
    k_scanB<<<1, 128>>>();
    k_scanC<<<98, 1024>>>();
    k_bucket<<<6250, 256>>>();
    k_gemm1<<<740, 128>>>(x0, W1);
    k_agg<<<12500, 256>>>(0, b1);
    k_stats1<<<256, 256>>>();
    k_gemm2<<<1480, 128>>>(W2, g1, be1);
    k_agg<<<12500, 256>>>(1, b2);
    k_final<<<3125, 256>>>(Wl, bl, out);
}